// round 13
// baseline (speedup 1.0000x reference)
#include <cuda_runtime.h>
#include <cstdint>
#include <math.h>

typedef unsigned int u32;
typedef unsigned long long u64;

#define BMAX 4096

// ---------------- device scratch ----------------
__device__ u32 g_q3[BMAX * 64];       // qact3 bits
__device__ u64 g_w2p[64 * 9];         // conv2 packed weights
__device__ u32 g_f2p[10 * 64];        // fc2 packed weights
__device__ u32 g_w1b[2048 * 1568];    // fc1 weights bf16 +/-1 pairs, [j][k/2]
__device__ u32 g_abf[BMAX * 1568];    // activations bf16 +/-1 pairs, [n][k/2], k = c*49+p
__device__ int  g_done[4];            // conv chunk completion counters
__device__ int   g_c1q[64];
__device__ float g_c1A[64], g_c1B[64];
__device__ float g_c2A[64], g_c2B[64];
__device__ float g_A3[2048], g_B3[2048];

// ---------------- helpers ----------------
__device__ __forceinline__ u32 smem_u32(const void* p) {
    u32 a;
    asm("{ .reg .u64 t; cvta.to.shared.u64 t, %1; cvt.u32.u64 %0, t; }" : "=r"(a) : "l"(p));
    return a;
}
#define CP_ASYNC16(dst, src) asm volatile("cp.async.cg.shared.global [%0], [%1], 16;" :: "r"(dst), "l"(src))
#define CP_COMMIT()          asm volatile("cp.async.commit_group;" ::: "memory")
#define SWZ128(o)            ((o) ^ (((o) >> 3) & 0x70))

__device__ __forceinline__ void ldsm4(u32& r0, u32& r1, u32& r2, u32& r3, u32 a) {
    asm volatile("ldmatrix.sync.aligned.m8n8.x4.shared.b16 {%0,%1,%2,%3}, [%4];"
        : "=r"(r0), "=r"(r1), "=r"(r2), "=r"(r3) : "r"(a));
}
__device__ __forceinline__ void hmma_bf16(float* d, u32 a0, u32 a1, u32 a2, u32 a3, u32 b0, u32 b1) {
    asm volatile("mma.sync.aligned.m16n8k16.row.col.f32.bf16.bf16.f32 "
        "{%0,%1,%2,%3}, {%4,%5,%6,%7}, {%8,%9}, {%0,%1,%2,%3};"
        : "+f"(d[0]), "+f"(d[1]), "+f"(d[2]), "+f"(d[3])
        : "r"(a0), "r"(a1), "r"(a2), "r"(a3), "r"(b0), "r"(b1));
}

// ---------------- prep ----------------
__global__ void prep_kernel(const float* __restrict__ fc1_w, const float* __restrict__ fc2_w,
                            const float* __restrict__ c2w,  const float* __restrict__ c1w,
                            const float* __restrict__ c1b,
                            const float* __restrict__ g1, const float* __restrict__ be1,
                            const float* __restrict__ mu1, const float* __restrict__ va1,
                            const float* __restrict__ c2b,
                            const float* __restrict__ g2, const float* __restrict__ be2,
                            const float* __restrict__ mu2, const float* __restrict__ va2,
                            const float* __restrict__ f1b,
                            const float* __restrict__ g3, const float* __restrict__ be3,
                            const float* __restrict__ mu3, const float* __restrict__ va3)
{
    if (blockIdx.x == 0 && threadIdx.x < 4) g_done[threadIdx.x] = 0;   // reset pipeline flags
    int i = blockIdx.x * blockDim.x + threadIdx.x;
    if (i < 2048 * 1568) {                     // fc1 -> bf16 +/-1 pairs (coalesced)
        u32 lo = (fc1_w[2 * (size_t)i]     >= 0.f) ? 0x3F80u : 0xBF80u;
        u32 hi = (fc1_w[2 * (size_t)i + 1] >= 0.f) ? 0x3F80u : 0xBF80u;
        g_w1b[i] = lo | (hi << 16);
        return;
    }
    int r = i - 2048 * 1568;
    if (r < 640) {
        int k = r / 64, wi = r % 64;
        const float* base = fc2_w + k * 2048 + wi * 32;
        u32 w = 0;
        #pragma unroll
        for (int l = 0; l < 32; l++) w |= (u32)(base[l] >= 0.f) << l;
        g_f2p[r] = w;
        return;
    }
    r -= 640;
    if (r < 576) {
        int c = r / 9, tap = r % 9;
        u64 w = 0;
        #pragma unroll
        for (int ci = 0; ci < 64; ci++)
            w |= (u64)(c2w[(c * 64 + ci) * 9 + tap] >= 0.f) << ci;
        g_w2p[r] = w;
        return;
    }
    r -= 576;
    if (r < 64) {
        int c = r;
        int m = 0;
        #pragma unroll
        for (int k = 0; k < 3; k++) {
            float a = c1w[c * 9 + k * 3], b = c1w[c * 9 + k * 3 + 1], cc = c1w[c * 9 + k * 3 + 2];
            int sa = (a >= 0.f), sb = (b >= 0.f), sc = (cc >= 0.f);
            int q = ((sa ^ sb) ? 2 : 0) | ((sa ^ sc) ? 1 : 0);
            m |= q << (2 * k);
            if (!sa) m |= 1 << (6 + k);
        }
        g_c1q[c] = m;
        float inv = g1[c] * (float)(1.0 / sqrt((double)va1[c] + 1e-5));
        g_c1A[c] = inv;
        g_c1B[c] = inv * c1b[c] + be1[c] - mu1[c] * inv;
        return;
    }
    r -= 64;
    if (r < 64) {
        int c = r;
        float inv = g2[c] * (float)(1.0 / sqrt((double)va2[c] + 1e-5));
        g_c2A[c] = inv;
        g_c2B[c] = inv * c2b[c] + be2[c] - mu2[c] * inv;
        return;
    }
    r -= 64;
    if (r < 2048) {
        int j = r;
        float inv = g3[j] * (float)(1.0 / sqrt((double)va3[j] + 1e-5));
        g_A3[j] = inv;
        g_B3[j] = inv * f1b[j] + be3[j] - mu3[j] * inv;
    }
}

// ---------------- conv body: conv1+pool+bn1+sign + conv2+pool+bn2+sign + bf16 expand ----------------
__device__ __forceinline__ void conv_body(const float* __restrict__ x, int n, int chunk)
{
    __shared__ float  xs[784];
    __shared__ float2 CF[4 * 30 * 14];
    __shared__ __align__(16) u64 sa[256];
    __shared__ u64 sw[576];
    __shared__ u64 sq[49];
    int t = threadIdx.x;
    const float* xg = x + (size_t)n * 784;
    for (int i = t; i < 784; i += 256) xs[i] = xg[i];
    sa[t] = 0;
    for (int i = t; i < 576; i += 256) sw[i] = g_w2p[i];
    __syncthreads();

    for (int i = t; i < 112; i += 256) {
        int pl = i / 28; int rr = (i / 14) & 1; int px = i % 14;
        CF[pl * 420 + (rr ? 29 : 0) * 14 + px] = make_float2(0.f, 0.f);
    }
    for (int i = t; i < 392; i += 256) {
        int ry = i / 14, px = i % 14;
        int x0 = 2 * px;
        float am = (x0 > 0)      ? xs[ry * 28 + x0 - 1] : 0.f;
        float b0 = xs[ry * 28 + x0];
        float b1 = xs[ry * 28 + x0 + 1];
        float ap = (x0 + 2 < 28) ? xs[ry * 28 + x0 + 2] : 0.f;
        int row = ry + 1;
        float s0a = am + b0, d0a = am - b0;
        float s1a = b0 + b1, d1a = b0 - b1;
        CF[0 * 420 + row * 14 + px] = make_float2(s0a + b1, s1a + ap);
        CF[1 * 420 + row * 14 + px] = make_float2(s0a - b1, s1a - ap);
        CF[2 * 420 + row * 14 + px] = make_float2(d0a + b1, d1a + ap);
        CF[3 * 420 + row * 14 + px] = make_float2(d0a - b1, d1a - ap);
    }
    __syncthreads();

    int w = t >> 5, lane = t & 31;
    int half = w & 1, wg = w >> 1;
    int c = half * 32 + lane;

    {
        int m = g_c1q[c];
        float A = g_c1A[c], Bc = g_c1B[c];
        int o0 = (m & 3) * 420;
        int o1 = ((m >> 2) & 3) * 420 + 14;
        int o2 = ((m >> 4) & 3) * 420 + 28;
        float s0 = (m & 0x40)  ? -1.f : 1.f;
        float s1 = (m & 0x80)  ? -1.f : 1.f;
        float s2 = (m & 0x100) ? -1.f : 1.f;

        for (int p = wg; p < 196; p += 4) {
            int py = p / 14, px = p % 14;
            int base = (2 * py) * 14 + px;
            float2 a0 = CF[o0 + base],      b0v = CF[o1 + base],      c0 = CF[o2 + base];
            float2 a1 = CF[o0 + base + 14], b1v = CF[o1 + base + 14], c1 = CF[o2 + base + 14];
            float v0x = fmaf(s0, a0.x, fmaf(s1, b0v.x, s2 * c0.x));
            float v0y = fmaf(s0, a0.y, fmaf(s1, b0v.y, s2 * c0.y));
            float v1x = fmaf(s0, a1.x, fmaf(s1, b1v.x, s2 * c1.x));
            float v1y = fmaf(s0, a1.y, fmaf(s1, b1v.y, s2 * c1.y));
            float mx = fmaxf(fmaxf(v0x, v0y), fmaxf(v1x, v1y));
            u32 mask = __ballot_sync(0xffffffffu, fmaf(A, mx, Bc) >= 0.f);
            if (lane == 0) ((u32*)&sa[(py + 1) * 16 + (px + 1)])[half] = mask;
        }
    }
    __syncthreads();

    {
        u64 wr[9];
        #pragma unroll
        for (int k = 0; k < 9; k++) wr[k] = sw[c * 9 + k];
        int e0 = 64 - 2 * __popcll(wr[0]);
        int e1 = 64 - 2 * __popcll(wr[1]);
        int e2 = 64 - 2 * __popcll(wr[2]);
        int e3 = 64 - 2 * __popcll(wr[3]);
        int e5 = 64 - 2 * __popcll(wr[5]);
        int e6 = 64 - 2 * __popcll(wr[6]);
        int e7 = 64 - 2 * __popcll(wr[7]);
        int e8 = 64 - 2 * __popcll(wr[8]);
        int ET = e0 + e1 + e2, EB = e6 + e7 + e8;
        int EL = e0 + e3 + e6, ER = e2 + e5 + e8;
        float A = g_c2A[c], Bc = g_c2B[c];

        for (int p = wg; p < 49; p += 4) {
            int py = p / 7, px = p % 7;
            int r0 = 2 * py, c0 = 2 * px;
            u64 blk[4][4];
            #pragma unroll
            for (int r = 0; r < 4; r++) {
                ulonglong2 lo = *(const ulonglong2*)&sa[(r0 + r) * 16 + c0];
                ulonglong2 hi = *(const ulonglong2*)&sa[(r0 + r) * 16 + c0 + 2];
                blk[r][0] = lo.x; blk[r][1] = lo.y; blk[r][2] = hi.x; blk[r][3] = hi.y;
            }
            int mx = -100000;
            #pragma unroll
            for (int yy = 0; yy < 2; yy++) {
                #pragma unroll
                for (int xx = 0; xx < 2; xx++) {
                    int pc = 0;
                    #pragma unroll
                    for (int r = 0; r < 3; r++) {
                        pc += __popcll(blk[yy + r][xx + 0] ^ wr[r * 3 + 0]);
                        pc += __popcll(blk[yy + r][xx + 1] ^ wr[r * 3 + 1]);
                        pc += __popcll(blk[yy + r][xx + 2] ^ wr[r * 3 + 2]);
                    }
                    int y = r0 + yy, xcv = c0 + xx;
                    int corr = 0;
                    if (y == 0)  corr += ET;
                    if (y == 13) corr += EB;
                    if (xcv == 0)  corr += EL;
                    if (xcv == 13) corr += ER;
                    if (y == 0 && xcv == 0)   corr -= e0;
                    if (y == 0 && xcv == 13)  corr -= e2;
                    if (y == 13 && xcv == 0)  corr -= e6;
                    if (y == 13 && xcv == 13) corr -= e8;
                    mx = max(mx, 576 - 2 * pc - corr);
                }
            }
            u32 mask = __ballot_sync(0xffffffffu, fmaf(A, (float)mx, Bc) >= 0.f);
            if (lane == 0) ((u32*)&sq[p])[half] = mask;
        }
    }
    __syncthreads();

    u32* row = g_abf + (size_t)n * 1568;
    for (int i = t; i < 1568; i += 256) {
        int ke0 = 2 * i, ke1 = ke0 + 1;
        int c0 = ke0 / 49, p0 = ke0 - c0 * 49;
        int c1 = ke1 / 49, p1 = ke1 - c1 * 49;
        u32 v0 = ((sq[p0] >> c0) & 1ull) ? 0x3F80u : 0xBF80u;
        u32 v1 = ((sq[p1] >> c1) & 1ull) ? 0x3F80u : 0xBF80u;
        row[i] = v0 | (v1 << 16);
    }
    __syncthreads();
    if (t == 0) {
        __threadfence();
        atomicAdd(&g_done[chunk], 1);
    }
}

// ---------------- fc1 body: bf16 HMMA, C[64n x 128j], warp tile 32x32 ----------------
__device__ __forceinline__ void fc1_body(int chunk, int local, char* smem)
{
    // wait for producer chunk
    if (threadIdx.x == 0) {
        volatile int* flag = g_done + chunk;
        while (*flag < 1024) { __nanosleep(200); }
    }
    __syncthreads();

    u32 sb = smem_u32(smem);
    u32 stA[2] = { sb, sb + 8192u };
    u32 stB[2] = { sb + 16384u, sb + 32768u };

    int t = threadIdx.x;
    int w = t >> 5, lane = t & 31;
    int nblk = chunk * 16 + (local & 15), jblk = local >> 4;
    int n0 = nblk * 64, j0 = jblk * 128;
    int warp_m = w >> 2, warp_n = w & 3;
    int g = lane >> 2, tig = lane & 3;

    const char* aBase = (const char*)g_abf + (size_t)n0 * 6272;
    const char* bBase = (const char*)g_w1b + (size_t)j0 * 6272;

    {
        #pragma unroll
        for (int s = 0; s < 2; s++) {
            int idx = t + s * 256;
            int row = idx >> 3, ch = idx & 7;
            CP_ASYNC16(stA[0] + SWZ128(row * 128 + ch * 16), aBase + (size_t)row * 6272 + ch * 16);
        }
        #pragma unroll
        for (int s = 0; s < 4; s++) {
            int idx = t + s * 256;
            int row = idx >> 3, ch = idx & 7;
            CP_ASYNC16(stB[0] + SWZ128(row * 128 + ch * 16), bBase + (size_t)row * 6272 + ch * 16);
        }
        CP_COMMIT();
    }

    float acc[2][4][4];
    #pragma unroll
    for (int mi = 0; mi < 2; mi++)
        #pragma unroll
        for (int ni = 0; ni < 4; ni++)
            #pragma unroll
            for (int cc = 0; cc < 4; cc++) acc[mi][ni][cc] = 0.f;

    int aRowL = warp_m * 32 + (lane & 15);
    int aHi = lane >> 4;
    int bRowL = warp_n * 32 + (lane & 7) + ((lane >> 4) & 1) * 8;
    int bHi = (lane >> 3) & 1;

    for (int c = 0; c < 49; c++) {
        int buf = c & 1;
        if (c + 1 < 49) {
            int nb = buf ^ 1;
            size_t koff = (size_t)(c + 1) * 128;
            #pragma unroll
            for (int s = 0; s < 2; s++) {
                int idx = t + s * 256;
                int row = idx >> 3, ch = idx & 7;
                CP_ASYNC16(stA[nb] + SWZ128(row * 128 + ch * 16), aBase + (size_t)row * 6272 + koff + ch * 16);
            }
            #pragma unroll
            for (int s = 0; s < 4; s++) {
                int idx = t + s * 256;
                int row = idx >> 3, ch = idx & 7;
                CP_ASYNC16(stB[nb] + SWZ128(row * 128 + ch * 16), bBase + (size_t)row * 6272 + koff + ch * 16);
            }
            CP_COMMIT();
            asm volatile("cp.async.wait_group 1;" ::: "memory");
        } else {
            asm volatile("cp.async.wait_group 0;" ::: "memory");
        }
        __syncthreads();

        #pragma unroll
        for (int ks = 0; ks < 4; ks++) {
            u32 af[2][4];
            #pragma unroll
            for (int mi = 0; mi < 2; mi++) {
                int row = aRowL + mi * 16;
                int ch = (ks * 2 + aHi) ^ (row & 7);
                ldsm4(af[mi][0], af[mi][1], af[mi][2], af[mi][3], stA[buf] + row * 128 + ch * 16);
            }
            u32 bf[2][4];
            #pragma unroll
            for (int np = 0; np < 2; np++) {
                int row = bRowL + np * 16;
                int ch = (ks * 2 + bHi) ^ (row & 7);
                ldsm4(bf[np][0], bf[np][1], bf[np][2], bf[np][3], stB[buf] + row * 128 + ch * 16);
            }
            #pragma unroll
            for (int mi = 0; mi < 2; mi++) {
                hmma_bf16(acc[mi][0], af[mi][0], af[mi][1], af[mi][2], af[mi][3], bf[0][0], bf[0][1]);
                hmma_bf16(acc[mi][1], af[mi][0], af[mi][1], af[mi][2], af[mi][3], bf[0][2], bf[0][3]);
                hmma_bf16(acc[mi][2], af[mi][0], af[mi][1], af[mi][2], af[mi][3], bf[1][0], bf[1][1]);
                hmma_bf16(acc[mi][3], af[mi][0], af[mi][1], af[mi][2], af[mi][3], bf[1][2], bf[1][3]);
            }
        }
        __syncthreads();
    }

    float A3v[4][2], B3v[4][2];
    #pragma unroll
    for (int ni = 0; ni < 4; ni++)
        #pragma unroll
        for (int cc = 0; cc < 2; cc++) {
            int j = j0 + warp_n * 32 + ni * 8 + tig * 2 + cc;
            A3v[ni][cc] = g_A3[j];
            B3v[ni][cc] = g_B3[j];
        }
    int wi = jblk * 4 + warp_n;
    #pragma unroll
    for (int mi = 0; mi < 2; mi++) {
        u32 v0 = 0, v1 = 0;
        #pragma unroll
        for (int ni = 0; ni < 4; ni++)
            #pragma unroll
            for (int cc = 0; cc < 2; cc++) {
                int pos = ni * 8 + tig * 2 + cc;
                v0 |= (u32)(fmaf(A3v[ni][cc], acc[mi][ni][cc],     B3v[ni][cc]) >= 0.f) << pos;
                v1 |= (u32)(fmaf(A3v[ni][cc], acc[mi][ni][2 + cc], B3v[ni][cc]) >= 0.f) << pos;
            }
        v0 |= __shfl_xor_sync(0xffffffffu, v0, 1);
        v0 |= __shfl_xor_sync(0xffffffffu, v0, 2);
        v1 |= __shfl_xor_sync(0xffffffffu, v1, 1);
        v1 |= __shfl_xor_sync(0xffffffffu, v1, 2);
        if (tig == 0) {
            int row0 = n0 + warp_m * 32 + mi * 16 + g;
            g_q3[(size_t)row0 * 64 + wi] = v0;
            g_q3[(size_t)(row0 + 8) * 64 + wi] = v1;
        }
    }
}

// ---------------- mega kernel: conv CTAs + fc1 CTAs, bid-ordered software pipeline ----------------
// layout: [conv0 1024][conv1 1024][fc1_0 256][conv2 1024][fc1_1 256][conv3 1024][fc1_2 256][fc1_3 256]
__global__ __launch_bounds__(256, 3) void mega_kernel(const float* __restrict__ x)
{
    extern __shared__ char dsmem[];
    int bid = blockIdx.x;
    int role, chunk, local;
    if      (bid < 1024) { role = 0; chunk = 0; local = bid; }
    else if (bid < 2048) { role = 0; chunk = 1; local = bid - 1024; }
    else if (bid < 2304) { role = 1; chunk = 0; local = bid - 2048; }
    else if (bid < 3328) { role = 0; chunk = 2; local = bid - 2304; }
    else if (bid < 3584) { role = 1; chunk = 1; local = bid - 3328; }
    else if (bid < 4608) { role = 0; chunk = 3; local = bid - 3584; }
    else if (bid < 4864) { role = 1; chunk = 2; local = bid - 4608; }
    else                 { role = 1; chunk = 3; local = bid - 4864; }

    if (role == 0) conv_body(x, chunk * 1024 + local, chunk);
    else           fc1_body(chunk, local, dsmem);
}

// ---------------- fc2 + scale ----------------
__global__ __launch_bounds__(256) void fc2_kernel(const float* __restrict__ fc2_b,
                                                  const float* __restrict__ scale,
                                                  float* __restrict__ out)
{
    __shared__ u32 q3[16 * 64];
    __shared__ u32 f2[640];
    int n0 = blockIdx.x * 16;
    int t = threadIdx.x;
    for (int i = t; i < 1024; i += 256) q3[i] = g_q3[n0 * 64 + i];
    for (int i = t; i < 640; i += 256) f2[i] = g_f2p[i];
    __syncthreads();
    if (t < 160) {
        int nl = t / 10, k = t % 10;
        int pc = 0;
        #pragma unroll 8
        for (int wi = 0; wi < 64; wi++) pc += __popc(q3[nl * 64 + wi] ^ f2[k * 64 + wi]);
        out[(n0 + nl) * 10 + k] = ((float)(2048 - 2 * pc) + fc2_b[k]) * scale[0];
    }
}

// ---------------- launch ----------------
extern "C" void kernel_launch(void* const* d_in, const int* in_sizes, int n_in,
                              void* d_out, int out_size)
{
    const float* x   = (const float*)d_in[0];
    const float* c1w = (const float*)d_in[1];
    const float* c1b = (const float*)d_in[2];
    const float* c2w = (const float*)d_in[3];
    const float* c2b = (const float*)d_in[4];
    const float* f1w = (const float*)d_in[5];
    const float* f1b = (const float*)d_in[6];
    const float* f2w = (const float*)d_in[7];
    const float* f2b = (const float*)d_in[8];
    const float* g1  = (const float*)d_in[9];
    const float* be1 = (const float*)d_in[10];
    const float* mu1 = (const float*)d_in[11];
    const float* va1 = (const float*)d_in[12];
    const float* g2  = (const float*)d_in[13];
    const float* be2 = (const float*)d_in[14];
    const float* mu2 = (const float*)d_in[15];
    const float* va2 = (const float*)d_in[16];
    const float* g3  = (const float*)d_in[17];
    const float* be3 = (const float*)d_in[18];
    const float* mu3 = (const float*)d_in[19];
    const float* va3 = (const float*)d_in[20];
    const float* scl = (const float*)d_in[21];

    int B = in_sizes[0] / 784;   // 4096

    cudaFuncSetAttribute(mega_kernel, cudaFuncAttributeMaxDynamicSharedMemorySize, 49152);

    int prep_items = 2048 * 1568 + 640 + 576 + 64 + 64 + 2048;
    prep_kernel<<<(prep_items + 255) / 256, 256>>>(f1w, f2w, c2w, c1w, c1b,
                                                   g1, be1, mu1, va1,
                                                   c2b, g2, be2, mu2, va2,
                                                   f1b, g3, be3, mu3, va3);
    mega_kernel<<<5120, 256, 49152>>>(x);
    fc2_kernel<<<B / 16, 256>>>(f2b, scl, (float*)d_out);
}

// round 14
// speedup vs baseline: 1.1837x; 1.1837x over previous
#include <cuda_runtime.h>
#include <cstdint>
#include <math.h>

typedef unsigned int u32;
typedef unsigned long long u64;

#define BMAX 4096

// ---------------- device scratch ----------------
__device__ u32 g_q3[BMAX * 64];       // qact3 bits
__device__ u64 g_w2p[64 * 9];         // conv2 packed weights
__device__ u32 g_f2p[10 * 64];        // fc2 packed weights
__device__ u32 g_w1b[2048 * 1568];    // fc1 weights bf16 +/-1 pairs, [j][k/2]
__device__ u32 g_abf[BMAX * 1568];    // activations bf16 +/-1 pairs, [n][k/2], k = c*49+p
__device__ int   g_c1q[64];
__device__ float g_c1A[64], g_c1B[64];
__device__ float g_c2A[64], g_c2B[64];
__device__ float g_A3[2048], g_B3[2048];

// ---------------- helpers ----------------
__device__ __forceinline__ u32 smem_u32(const void* p) {
    u32 a;
    asm("{ .reg .u64 t; cvta.to.shared.u64 t, %1; cvt.u32.u64 %0, t; }" : "=r"(a) : "l"(p));
    return a;
}
#define CP_ASYNC16(dst, src) asm volatile("cp.async.cg.shared.global [%0], [%1], 16;" :: "r"(dst), "l"(src))
#define CP_COMMIT()          asm volatile("cp.async.commit_group;" ::: "memory")
#define SWZ128(o)            ((o) ^ (((o) >> 3) & 0x70))

__device__ __forceinline__ void ldsm4(u32& r0, u32& r1, u32& r2, u32& r3, u32 a) {
    asm volatile("ldmatrix.sync.aligned.m8n8.x4.shared.b16 {%0,%1,%2,%3}, [%4];"
        : "=r"(r0), "=r"(r1), "=r"(r2), "=r"(r3) : "r"(a));
}
__device__ __forceinline__ void hmma_bf16(float* d, u32 a0, u32 a1, u32 a2, u32 a3, u32 b0, u32 b1) {
    asm volatile("mma.sync.aligned.m16n8k16.row.col.f32.bf16.bf16.f32 "
        "{%0,%1,%2,%3}, {%4,%5,%6,%7}, {%8,%9}, {%0,%1,%2,%3};"
        : "+f"(d[0]), "+f"(d[1]), "+f"(d[2]), "+f"(d[3])
        : "r"(a0), "r"(a1), "r"(a2), "r"(a3), "r"(b0), "r"(b1));
}

// ---------------- prep ----------------
__global__ void prep_kernel(const float* __restrict__ fc1_w, const float* __restrict__ fc2_w,
                            const float* __restrict__ c2w,  const float* __restrict__ c1w,
                            const float* __restrict__ c1b,
                            const float* __restrict__ g1, const float* __restrict__ be1,
                            const float* __restrict__ mu1, const float* __restrict__ va1,
                            const float* __restrict__ c2b,
                            const float* __restrict__ g2, const float* __restrict__ be2,
                            const float* __restrict__ mu2, const float* __restrict__ va2,
                            const float* __restrict__ f1b,
                            const float* __restrict__ g3, const float* __restrict__ be3,
                            const float* __restrict__ mu3, const float* __restrict__ va3)
{
    int i = blockIdx.x * blockDim.x + threadIdx.x;
    if (i < 2048 * 784) {                      // fc1 -> bf16 +/-1 pairs, float4 per thread
        float4 v = ((const float4*)fc1_w)[i];
        u32 w0 = ((v.x >= 0.f) ? 0x3F80u : 0xBF80u) | (((v.y >= 0.f) ? 0x3F80u : 0xBF80u) << 16);
        u32 w1 = ((v.z >= 0.f) ? 0x3F80u : 0xBF80u) | (((v.w >= 0.f) ? 0x3F80u : 0xBF80u) << 16);
        *(u64*)&g_w1b[2 * (size_t)i] = (u64)w0 | ((u64)w1 << 32);
        return;
    }
    int r = i - 2048 * 784;
    if (r < 640) {
        int k = r / 64, wi = r % 64;
        const float* base = fc2_w + k * 2048 + wi * 32;
        u32 w = 0;
        #pragma unroll
        for (int l = 0; l < 32; l++) w |= (u32)(base[l] >= 0.f) << l;
        g_f2p[r] = w;
        return;
    }
    r -= 640;
    if (r < 576) {
        int c = r / 9, tap = r % 9;
        u64 w = 0;
        #pragma unroll
        for (int ci = 0; ci < 64; ci++)
            w |= (u64)(c2w[(c * 64 + ci) * 9 + tap] >= 0.f) << ci;
        g_w2p[r] = w;
        return;
    }
    r -= 576;
    if (r < 64) {
        int c = r;
        int m = 0;
        #pragma unroll
        for (int k = 0; k < 3; k++) {
            float a = c1w[c * 9 + k * 3], b = c1w[c * 9 + k * 3 + 1], cc = c1w[c * 9 + k * 3 + 2];
            int sa = (a >= 0.f), sb = (b >= 0.f), sc = (cc >= 0.f);
            int q = ((sa ^ sb) ? 2 : 0) | ((sa ^ sc) ? 1 : 0);
            m |= q << (2 * k);
            if (!sa) m |= 1 << (6 + k);
        }
        g_c1q[c] = m;
        float inv = g1[c] * (float)(1.0 / sqrt((double)va1[c] + 1e-5));
        g_c1A[c] = inv;
        g_c1B[c] = inv * c1b[c] + be1[c] - mu1[c] * inv;
        return;
    }
    r -= 64;
    if (r < 64) {
        int c = r;
        float inv = g2[c] * (float)(1.0 / sqrt((double)va2[c] + 1e-5));
        g_c2A[c] = inv;
        g_c2B[c] = inv * c2b[c] + be2[c] - mu2[c] * inv;
        return;
    }
    r -= 64;
    if (r < 2048) {
        int j = r;
        float inv = g3[j] * (float)(1.0 / sqrt((double)va3[j] + 1e-5));
        g_A3[j] = inv;
        g_B3[j] = inv * f1b[j] + be3[j] - mu3[j] * inv;
    }
}

// ---------------- fused conv: 2 samples per CTA, weights/meta loaded once ----------------
__global__ __launch_bounds__(256) void conv_kernel(const float* __restrict__ x)
{
    __shared__ float  xs[784];
    __shared__ float2 CF[4 * 30 * 14];
    __shared__ __align__(16) u64 sa[256];
    __shared__ u64 sw[576];
    __shared__ u64 sq[49];
    int t = threadIdx.x;
    int w = t >> 5, lane = t & 31;
    int half = w & 1, wg = w >> 1;
    int c = half * 32 + lane;

    sa[t] = 0;                                       // pad cells stay zero across both samples
    for (int i = t; i < 576; i += 256) sw[i] = g_w2p[i];
    __syncthreads();

    // per-channel invariants (once per CTA)
    int m1 = g_c1q[c];
    float A1 = g_c1A[c], B1 = g_c1B[c];
    int o0 = (m1 & 3) * 420;
    int o1 = ((m1 >> 2) & 3) * 420 + 14;
    int o2 = ((m1 >> 4) & 3) * 420 + 28;
    float s0 = (m1 & 0x40)  ? -1.f : 1.f;
    float s1 = (m1 & 0x80)  ? -1.f : 1.f;
    float s2 = (m1 & 0x100) ? -1.f : 1.f;

    u64 wr[9];
    #pragma unroll
    for (int k = 0; k < 9; k++) wr[k] = sw[c * 9 + k];
    int e0 = 64 - 2 * __popcll(wr[0]);
    int e1 = 64 - 2 * __popcll(wr[1]);
    int e2 = 64 - 2 * __popcll(wr[2]);
    int e3 = 64 - 2 * __popcll(wr[3]);
    int e5 = 64 - 2 * __popcll(wr[5]);
    int e6 = 64 - 2 * __popcll(wr[6]);
    int e7 = 64 - 2 * __popcll(wr[7]);
    int e8 = 64 - 2 * __popcll(wr[8]);
    int ET = e0 + e1 + e2, EB = e6 + e7 + e8;
    int EL = e0 + e3 + e6, ER = e2 + e5 + e8;
    float A2 = g_c2A[c], B2 = g_c2B[c];

    for (int s = 0; s < 2; s++) {
        int n = blockIdx.x * 2 + s;
        const float* xg = x + (size_t)n * 784;
        for (int i = t; i < 784; i += 256) xs[i] = xg[i];
        __syncthreads();

        for (int i = t; i < 112; i += 256) {
            int pl = i / 28; int rr = (i / 14) & 1; int px = i % 14;
            CF[pl * 420 + (rr ? 29 : 0) * 14 + px] = make_float2(0.f, 0.f);
        }
        for (int i = t; i < 392; i += 256) {
            int ry = i / 14, px = i % 14;
            int x0 = 2 * px;
            float am = (x0 > 0)      ? xs[ry * 28 + x0 - 1] : 0.f;
            float b0 = xs[ry * 28 + x0];
            float b1 = xs[ry * 28 + x0 + 1];
            float ap = (x0 + 2 < 28) ? xs[ry * 28 + x0 + 2] : 0.f;
            int row = ry + 1;
            float s0a = am + b0, d0a = am - b0;
            float s1a = b0 + b1, d1a = b0 - b1;
            CF[0 * 420 + row * 14 + px] = make_float2(s0a + b1, s1a + ap);
            CF[1 * 420 + row * 14 + px] = make_float2(s0a - b1, s1a - ap);
            CF[2 * 420 + row * 14 + px] = make_float2(d0a + b1, d1a + ap);
            CF[3 * 420 + row * 14 + px] = make_float2(d0a - b1, d1a - ap);
        }
        __syncthreads();

        // ---- conv1 -> padded sa tile ----
        for (int p = wg; p < 196; p += 4) {
            int py = p / 14, px = p % 14;
            int base = (2 * py) * 14 + px;
            float2 a0 = CF[o0 + base],      b0v = CF[o1 + base],      c0 = CF[o2 + base];
            float2 a1 = CF[o0 + base + 14], b1v = CF[o1 + base + 14], c1 = CF[o2 + base + 14];
            float v0x = fmaf(s0, a0.x, fmaf(s1, b0v.x, s2 * c0.x));
            float v0y = fmaf(s0, a0.y, fmaf(s1, b0v.y, s2 * c0.y));
            float v1x = fmaf(s0, a1.x, fmaf(s1, b1v.x, s2 * c1.x));
            float v1y = fmaf(s0, a1.y, fmaf(s1, b1v.y, s2 * c1.y));
            float mx = fmaxf(fmaxf(v0x, v0y), fmaxf(v1x, v1y));
            u32 mask = __ballot_sync(0xffffffffu, fmaf(A1, mx, B1) >= 0.f);
            if (lane == 0) ((u32*)&sa[(py + 1) * 16 + (px + 1)])[half] = mask;
        }
        __syncthreads();

        // ---- conv2 (register-blocked 4x4) ----
        for (int p = wg; p < 49; p += 4) {
            int py = p / 7, px = p % 7;
            int r0 = 2 * py, c0 = 2 * px;
            u64 blk[4][4];
            #pragma unroll
            for (int r = 0; r < 4; r++) {
                ulonglong2 lo = *(const ulonglong2*)&sa[(r0 + r) * 16 + c0];
                ulonglong2 hi = *(const ulonglong2*)&sa[(r0 + r) * 16 + c0 + 2];
                blk[r][0] = lo.x; blk[r][1] = lo.y; blk[r][2] = hi.x; blk[r][3] = hi.y;
            }
            int mx = -100000;
            #pragma unroll
            for (int yy = 0; yy < 2; yy++) {
                #pragma unroll
                for (int xx = 0; xx < 2; xx++) {
                    int pc = 0;
                    #pragma unroll
                    for (int r = 0; r < 3; r++) {
                        pc += __popcll(blk[yy + r][xx + 0] ^ wr[r * 3 + 0]);
                        pc += __popcll(blk[yy + r][xx + 1] ^ wr[r * 3 + 1]);
                        pc += __popcll(blk[yy + r][xx + 2] ^ wr[r * 3 + 2]);
                    }
                    int y = r0 + yy, xcv = c0 + xx;
                    int corr = 0;
                    if (y == 0)  corr += ET;
                    if (y == 13) corr += EB;
                    if (xcv == 0)  corr += EL;
                    if (xcv == 13) corr += ER;
                    if (y == 0 && xcv == 0)   corr -= e0;
                    if (y == 0 && xcv == 13)  corr -= e2;
                    if (y == 13 && xcv == 0)  corr -= e6;
                    if (y == 13 && xcv == 13) corr -= e8;
                    mx = max(mx, 576 - 2 * pc - corr);
                }
            }
            u32 mask = __ballot_sync(0xffffffffu, fmaf(A2, (float)mx, B2) >= 0.f);
            if (lane == 0) ((u32*)&sq[p])[half] = mask;
        }
        __syncthreads();

        // ---- expand: bits -> bf16 +/-1 pairs ----
        u32* row = g_abf + (size_t)n * 1568;
        for (int i = t; i < 1568; i += 256) {
            int ke0 = 2 * i, ke1 = ke0 + 1;
            int c0 = ke0 / 49, p0 = ke0 - c0 * 49;
            int c1 = ke1 / 49, p1 = ke1 - c1 * 49;
            u32 v0 = ((sq[p0] >> c0) & 1ull) ? 0x3F80u : 0xBF80u;
            u32 v1 = ((sq[p1] >> c1) & 1ull) ? 0x3F80u : 0xBF80u;
            row[i] = v0 | (v1 << 16);
        }
        __syncthreads();
    }
}

// ---------------- fc1 via bf16 HMMA: C[64n x 128j] per CTA, warp tile 32x32 ----------------
// 8 warps (2 M x 4 N). dyn smem: A 2x8KB @0, B 2x16KB @16K = 48KB -> 3 CTAs/SM.
__global__ __launch_bounds__(256, 3) void fc1_hmma_kernel()
{
    extern __shared__ char smem[];
    u32 sb = smem_u32(smem);
    u32 stA[2] = { sb, sb + 8192u };
    u32 stB[2] = { sb + 16384u, sb + 32768u };

    int t = threadIdx.x;
    int w = t >> 5, lane = t & 31;
    int bx = blockIdx.x;
    int nblk = bx & 63, jblk = bx >> 6;      // 64 x 16 CTAs
    int n0 = nblk * 64, j0 = jblk * 128;
    int warp_m = w >> 2, warp_n = w & 3;     // 2 x 4
    int g = lane >> 2, tig = lane & 3;

    const char* aBase = (const char*)g_abf + (size_t)n0 * 6272;
    const char* bBase = (const char*)g_w1b + (size_t)j0 * 6272;

    {
        #pragma unroll
        for (int s = 0; s < 2; s++) {
            int idx = t + s * 256;
            int row = idx >> 3, ch = idx & 7;
            CP_ASYNC16(stA[0] + SWZ128(row * 128 + ch * 16), aBase + (size_t)row * 6272 + ch * 16);
        }
        #pragma unroll
        for (int s = 0; s < 4; s++) {
            int idx = t + s * 256;
            int row = idx >> 3, ch = idx & 7;
            CP_ASYNC16(stB[0] + SWZ128(row * 128 + ch * 16), bBase + (size_t)row * 6272 + ch * 16);
        }
        CP_COMMIT();
    }

    float acc[2][4][4];
    #pragma unroll
    for (int mi = 0; mi < 2; mi++)
        #pragma unroll
        for (int ni = 0; ni < 4; ni++)
            #pragma unroll
            for (int cc = 0; cc < 4; cc++) acc[mi][ni][cc] = 0.f;

    int aRowL = warp_m * 32 + (lane & 15);
    int aHi = lane >> 4;
    int bRowL = warp_n * 32 + (lane & 7) + ((lane >> 4) & 1) * 8;
    int bHi = (lane >> 3) & 1;

    for (int c = 0; c < 49; c++) {
        int buf = c & 1;
        if (c + 1 < 49) {
            int nb = buf ^ 1;
            size_t koff = (size_t)(c + 1) * 128;
            #pragma unroll
            for (int s = 0; s < 2; s++) {
                int idx = t + s * 256;
                int row = idx >> 3, ch = idx & 7;
                CP_ASYNC16(stA[nb] + SWZ128(row * 128 + ch * 16), aBase + (size_t)row * 6272 + koff + ch * 16);
            }
            #pragma unroll
            for (int s = 0; s < 4; s++) {
                int idx = t + s * 256;
                int row = idx >> 3, ch = idx & 7;
                CP_ASYNC16(stB[nb] + SWZ128(row * 128 + ch * 16), bBase + (size_t)row * 6272 + koff + ch * 16);
            }
            CP_COMMIT();
            asm volatile("cp.async.wait_group 1;" ::: "memory");
        } else {
            asm volatile("cp.async.wait_group 0;" ::: "memory");
        }
        __syncthreads();

        #pragma unroll
        for (int ks = 0; ks < 4; ks++) {
            u32 af[2][4];
            #pragma unroll
            for (int mi = 0; mi < 2; mi++) {
                int row = aRowL + mi * 16;
                int ch = (ks * 2 + aHi) ^ (row & 7);
                ldsm4(af[mi][0], af[mi][1], af[mi][2], af[mi][3], stA[buf] + row * 128 + ch * 16);
            }
            u32 bf[2][4];
            #pragma unroll
            for (int np = 0; np < 2; np++) {
                int row = bRowL + np * 16;
                int ch = (ks * 2 + bHi) ^ (row & 7);
                ldsm4(bf[np][0], bf[np][1], bf[np][2], bf[np][3], stB[buf] + row * 128 + ch * 16);
            }
            #pragma unroll
            for (int mi = 0; mi < 2; mi++) {
                hmma_bf16(acc[mi][0], af[mi][0], af[mi][1], af[mi][2], af[mi][3], bf[0][0], bf[0][1]);
                hmma_bf16(acc[mi][1], af[mi][0], af[mi][1], af[mi][2], af[mi][3], bf[0][2], bf[0][3]);
                hmma_bf16(acc[mi][2], af[mi][0], af[mi][1], af[mi][2], af[mi][3], bf[1][0], bf[1][1]);
                hmma_bf16(acc[mi][3], af[mi][0], af[mi][1], af[mi][2], af[mi][3], bf[1][2], bf[1][3]);
            }
        }
        __syncthreads();
    }

    float A3v[4][2], B3v[4][2];
    #pragma unroll
    for (int ni = 0; ni < 4; ni++)
        #pragma unroll
        for (int cc = 0; cc < 2; cc++) {
            int j = j0 + warp_n * 32 + ni * 8 + tig * 2 + cc;
            A3v[ni][cc] = g_A3[j];
            B3v[ni][cc] = g_B3[j];
        }
    int wi = jblk * 4 + warp_n;
    #pragma unroll
    for (int mi = 0; mi < 2; mi++) {
        u32 v0 = 0, v1 = 0;
        #pragma unroll
        for (int ni = 0; ni < 4; ni++)
            #pragma unroll
            for (int cc = 0; cc < 2; cc++) {
                int pos = ni * 8 + tig * 2 + cc;
                v0 |= (u32)(fmaf(A3v[ni][cc], acc[mi][ni][cc],     B3v[ni][cc]) >= 0.f) << pos;
                v1 |= (u32)(fmaf(A3v[ni][cc], acc[mi][ni][2 + cc], B3v[ni][cc]) >= 0.f) << pos;
            }
        v0 |= __shfl_xor_sync(0xffffffffu, v0, 1);
        v0 |= __shfl_xor_sync(0xffffffffu, v0, 2);
        v1 |= __shfl_xor_sync(0xffffffffu, v1, 1);
        v1 |= __shfl_xor_sync(0xffffffffu, v1, 2);
        if (tig == 0) {
            int row0 = n0 + warp_m * 32 + mi * 16 + g;
            g_q3[(size_t)row0 * 64 + wi] = v0;
            g_q3[(size_t)(row0 + 8) * 64 + wi] = v1;
        }
    }
}

// ---------------- fc2 + scale ----------------
__global__ __launch_bounds__(256) void fc2_kernel(const float* __restrict__ fc2_b,
                                                  const float* __restrict__ scale,
                                                  float* __restrict__ out)
{
    __shared__ u32 q3[16 * 64];
    __shared__ u32 f2[640];
    int n0 = blockIdx.x * 16;
    int t = threadIdx.x;
    for (int i = t; i < 1024; i += 256) q3[i] = g_q3[n0 * 64 + i];
    for (int i = t; i < 640; i += 256) f2[i] = g_f2p[i];
    __syncthreads();
    if (t < 160) {
        int nl = t / 10, k = t % 10;
        int pc = 0;
        #pragma unroll 8
        for (int wi = 0; wi < 64; wi++) pc += __popc(q3[nl * 64 + wi] ^ f2[k * 64 + wi]);
        out[(n0 + nl) * 10 + k] = ((float)(2048 - 2 * pc) + fc2_b[k]) * scale[0];
    }
}

// ---------------- launch ----------------
extern "C" void kernel_launch(void* const* d_in, const int* in_sizes, int n_in,
                              void* d_out, int out_size)
{
    const float* x   = (const float*)d_in[0];
    const float* c1w = (const float*)d_in[1];
    const float* c1b = (const float*)d_in[2];
    const float* c2w = (const float*)d_in[3];
    const float* c2b = (const float*)d_in[4];
    const float* f1w = (const float*)d_in[5];
    const float* f1b = (const float*)d_in[6];
    const float* f2w = (const float*)d_in[7];
    const float* f2b = (const float*)d_in[8];
    const float* g1  = (const float*)d_in[9];
    const float* be1 = (const float*)d_in[10];
    const float* mu1 = (const float*)d_in[11];
    const float* va1 = (const float*)d_in[12];
    const float* g2  = (const float*)d_in[13];
    const float* be2 = (const float*)d_in[14];
    const float* mu2 = (const float*)d_in[15];
    const float* va2 = (const float*)d_in[16];
    const float* g3  = (const float*)d_in[17];
    const float* be3 = (const float*)d_in[18];
    const float* mu3 = (const float*)d_in[19];
    const float* va3 = (const float*)d_in[20];
    const float* scl = (const float*)d_in[21];

    int B = in_sizes[0] / 784;   // 4096

    cudaFuncSetAttribute(fc1_hmma_kernel, cudaFuncAttributeMaxDynamicSharedMemorySize, 49152);

    int prep_items = 2048 * 784 + 640 + 576 + 64 + 64 + 2048;
    prep_kernel<<<(prep_items + 255) / 256, 256>>>(f1w, f2w, c2w, c1w, c1b,
                                                   g1, be1, mu1, va1,
                                                   c2b, g2, be2, mu2, va2,
                                                   f1b, g3, be3, mu3, va3);
    conv_kernel<<<B / 2, 256>>>(x);
    fc1_hmma_kernel<<<(B / 64) * 16, 256, 49152>>>();
    fc2_kernel<<<B / 16, 256>>>(f2b, scl, (float*)d_out);
}

// round 15
// speedup vs baseline: 1.2649x; 1.0686x over previous
#include <cuda_runtime.h>
#include <cstdint>
#include <math.h>

typedef unsigned int u32;
typedef unsigned long long u64;

#define BMAX 4096

// ---------------- device scratch ----------------
__device__ u32 g_q3[BMAX * 64];       // qact3 bits
__device__ u64 g_w2p[64 * 9];         // conv2 packed weights
__device__ u32 g_f2p[10 * 64];        // fc2 packed weights
__device__ u32 g_w1b[2048 * 1568];    // fc1 weights bf16 +/-1 pairs, [j][k/2]
__device__ u32 g_abf[BMAX * 1568];    // activations bf16 +/-1 pairs, [n][k/2], k = c*49+p
__device__ int   g_c1q[64];
__device__ float g_c1A[64], g_c1B[64];
__device__ float g_c2A[64], g_c2B[64];
__device__ float g_A3[2048], g_B3[2048];

// ---------------- helpers ----------------
__device__ __forceinline__ u32 smem_u32(const void* p) {
    u32 a;
    asm("{ .reg .u64 t; cvta.to.shared.u64 t, %1; cvt.u32.u64 %0, t; }" : "=r"(a) : "l"(p));
    return a;
}
#define CP_ASYNC16(dst, src) asm volatile("cp.async.cg.shared.global [%0], [%1], 16;" :: "r"(dst), "l"(src))
#define CP_COMMIT()          asm volatile("cp.async.commit_group;" ::: "memory")
#define SWZ128(o)            ((o) ^ (((o) >> 3) & 0x70))

__device__ __forceinline__ void ldsm4(u32& r0, u32& r1, u32& r2, u32& r3, u32 a) {
    asm volatile("ldmatrix.sync.aligned.m8n8.x4.shared.b16 {%0,%1,%2,%3}, [%4];"
        : "=r"(r0), "=r"(r1), "=r"(r2), "=r"(r3) : "r"(a));
}
__device__ __forceinline__ void hmma_bf16(float* d, u32 a0, u32 a1, u32 a2, u32 a3, u32 b0, u32 b1) {
    asm volatile("mma.sync.aligned.m16n8k16.row.col.f32.bf16.bf16.f32 "
        "{%0,%1,%2,%3}, {%4,%5,%6,%7}, {%8,%9}, {%0,%1,%2,%3};"
        : "+f"(d[0]), "+f"(d[1]), "+f"(d[2]), "+f"(d[3])
        : "r"(a0), "r"(a1), "r"(a2), "r"(a3), "r"(b0), "r"(b1));
}

// ---------------- prep (float4 fc1 pack) ----------------
__global__ void prep_kernel(const float* __restrict__ fc1_w, const float* __restrict__ fc2_w,
                            const float* __restrict__ c2w,  const float* __restrict__ c1w,
                            const float* __restrict__ c1b,
                            const float* __restrict__ g1, const float* __restrict__ be1,
                            const float* __restrict__ mu1, const float* __restrict__ va1,
                            const float* __restrict__ c2b,
                            const float* __restrict__ g2, const float* __restrict__ be2,
                            const float* __restrict__ mu2, const float* __restrict__ va2,
                            const float* __restrict__ f1b,
                            const float* __restrict__ g3, const float* __restrict__ be3,
                            const float* __restrict__ mu3, const float* __restrict__ va3)
{
    int i = blockIdx.x * blockDim.x + threadIdx.x;
    if (i < 2048 * 784) {                      // fc1 -> bf16 +/-1 pairs, float4 per thread
        float4 v = ((const float4*)fc1_w)[i];
        u32 w0 = ((v.x >= 0.f) ? 0x3F80u : 0xBF80u) | (((v.y >= 0.f) ? 0x3F80u : 0xBF80u) << 16);
        u32 w1 = ((v.z >= 0.f) ? 0x3F80u : 0xBF80u) | (((v.w >= 0.f) ? 0x3F80u : 0xBF80u) << 16);
        *(u64*)&g_w1b[2 * (size_t)i] = (u64)w0 | ((u64)w1 << 32);
        return;
    }
    int r = i - 2048 * 784;
    if (r < 640) {
        int k = r / 64, wi = r % 64;
        const float* base = fc2_w + k * 2048 + wi * 32;
        u32 w = 0;
        #pragma unroll
        for (int l = 0; l < 32; l++) w |= (u32)(base[l] >= 0.f) << l;
        g_f2p[r] = w;
        return;
    }
    r -= 640;
    if (r < 576) {
        int c = r / 9, tap = r % 9;
        u64 w = 0;
        #pragma unroll
        for (int ci = 0; ci < 64; ci++)
            w |= (u64)(c2w[(c * 64 + ci) * 9 + tap] >= 0.f) << ci;
        g_w2p[r] = w;
        return;
    }
    r -= 576;
    if (r < 64) {
        int c = r;
        int m = 0;
        #pragma unroll
        for (int k = 0; k < 3; k++) {
            float a = c1w[c * 9 + k * 3], b = c1w[c * 9 + k * 3 + 1], cc = c1w[c * 9 + k * 3 + 2];
            int sa = (a >= 0.f), sb = (b >= 0.f), sc = (cc >= 0.f);
            int q = ((sa ^ sb) ? 2 : 0) | ((sa ^ sc) ? 1 : 0);
            m |= q << (2 * k);
            if (!sa) m |= 1 << (6 + k);
        }
        g_c1q[c] = m;
        float inv = g1[c] * (float)(1.0 / sqrt((double)va1[c] + 1e-5));
        g_c1A[c] = inv;
        g_c1B[c] = inv * c1b[c] + be1[c] - mu1[c] * inv;
        return;
    }
    r -= 64;
    if (r < 64) {
        int c = r;
        float inv = g2[c] * (float)(1.0 / sqrt((double)va2[c] + 1e-5));
        g_c2A[c] = inv;
        g_c2B[c] = inv * c2b[c] + be2[c] - mu2[c] * inv;
        return;
    }
    r -= 64;
    if (r < 2048) {
        int j = r;
        float inv = g3[j] * (float)(1.0 / sqrt((double)va3[j] + 1e-5));
        g_A3[j] = inv;
        g_B3[j] = inv * f1b[j] + be3[j] - mu3[j] * inv;
    }
}

// ---------------- fused conv: 1 sample per CTA (R12-proven) ----------------
__global__ __launch_bounds__(256) void conv_kernel(const float* __restrict__ x)
{
    __shared__ float  xs[784];
    __shared__ float2 CF[4 * 30 * 14];
    __shared__ __align__(16) u64 sa[256];
    __shared__ u64 sw[576];
    __shared__ u64 sq[49];
    int n = blockIdx.x;
    int t = threadIdx.x;
    const float* xg = x + (size_t)n * 784;
    for (int i = t; i < 784; i += 256) xs[i] = xg[i];
    sa[t] = 0;
    for (int i = t; i < 576; i += 256) sw[i] = g_w2p[i];
    __syncthreads();

    for (int i = t; i < 112; i += 256) {
        int pl = i / 28; int rr = (i / 14) & 1; int px = i % 14;
        CF[pl * 420 + (rr ? 29 : 0) * 14 + px] = make_float2(0.f, 0.f);
    }
    for (int i = t; i < 392; i += 256) {
        int ry = i / 14, px = i % 14;
        int x0 = 2 * px;
        float am = (x0 > 0)      ? xs[ry * 28 + x0 - 1] : 0.f;
        float b0 = xs[ry * 28 + x0];
        float b1 = xs[ry * 28 + x0 + 1];
        float ap = (x0 + 2 < 28) ? xs[ry * 28 + x0 + 2] : 0.f;
        int row = ry + 1;
        float s0a = am + b0, d0a = am - b0;
        float s1a = b0 + b1, d1a = b0 - b1;
        CF[0 * 420 + row * 14 + px] = make_float2(s0a + b1, s1a + ap);
        CF[1 * 420 + row * 14 + px] = make_float2(s0a - b1, s1a - ap);
        CF[2 * 420 + row * 14 + px] = make_float2(d0a + b1, d1a + ap);
        CF[3 * 420 + row * 14 + px] = make_float2(d0a - b1, d1a - ap);
    }
    __syncthreads();

    int w = t >> 5, lane = t & 31;
    int half = w & 1, wg = w >> 1;
    int c = half * 32 + lane;

    // ---- conv1 ----
    {
        int m = g_c1q[c];
        float A = g_c1A[c], Bc = g_c1B[c];
        int o0 = (m & 3) * 420;
        int o1 = ((m >> 2) & 3) * 420 + 14;
        int o2 = ((m >> 4) & 3) * 420 + 28;
        float s0 = (m & 0x40)  ? -1.f : 1.f;
        float s1 = (m & 0x80)  ? -1.f : 1.f;
        float s2 = (m & 0x100) ? -1.f : 1.f;

        for (int p = wg; p < 196; p += 4) {
            int py = p / 14, px = p % 14;
            int base = (2 * py) * 14 + px;
            float2 a0 = CF[o0 + base],      b0v = CF[o1 + base],      c0 = CF[o2 + base];
            float2 a1 = CF[o0 + base + 14], b1v = CF[o1 + base + 14], c1 = CF[o2 + base + 14];
            float v0x = fmaf(s0, a0.x, fmaf(s1, b0v.x, s2 * c0.x));
            float v0y = fmaf(s0, a0.y, fmaf(s1, b0v.y, s2 * c0.y));
            float v1x = fmaf(s0, a1.x, fmaf(s1, b1v.x, s2 * c1.x));
            float v1y = fmaf(s0, a1.y, fmaf(s1, b1v.y, s2 * c1.y));
            float mx = fmaxf(fmaxf(v0x, v0y), fmaxf(v1x, v1y));
            u32 mask = __ballot_sync(0xffffffffu, fmaf(A, mx, Bc) >= 0.f);
            if (lane == 0) ((u32*)&sa[(py + 1) * 16 + (px + 1)])[half] = mask;
        }
    }
    __syncthreads();

    // ---- conv2 (register-blocked 4x4) ----
    {
        u64 wr[9];
        #pragma unroll
        for (int k = 0; k < 9; k++) wr[k] = sw[c * 9 + k];
        int e0 = 64 - 2 * __popcll(wr[0]);
        int e1 = 64 - 2 * __popcll(wr[1]);
        int e2 = 64 - 2 * __popcll(wr[2]);
        int e3 = 64 - 2 * __popcll(wr[3]);
        int e5 = 64 - 2 * __popcll(wr[5]);
        int e6 = 64 - 2 * __popcll(wr[6]);
        int e7 = 64 - 2 * __popcll(wr[7]);
        int e8 = 64 - 2 * __popcll(wr[8]);
        int ET = e0 + e1 + e2, EB = e6 + e7 + e8;
        int EL = e0 + e3 + e6, ER = e2 + e5 + e8;
        float A = g_c2A[c], Bc = g_c2B[c];

        for (int p = wg; p < 49; p += 4) {
            int py = p / 7, px = p % 7;
            int r0 = 2 * py, c0 = 2 * px;
            u64 blk[4][4];
            #pragma unroll
            for (int r = 0; r < 4; r++) {
                ulonglong2 lo = *(const ulonglong2*)&sa[(r0 + r) * 16 + c0];
                ulonglong2 hi = *(const ulonglong2*)&sa[(r0 + r) * 16 + c0 + 2];
                blk[r][0] = lo.x; blk[r][1] = lo.y; blk[r][2] = hi.x; blk[r][3] = hi.y;
            }
            int mx = -100000;
            #pragma unroll
            for (int yy = 0; yy < 2; yy++) {
                #pragma unroll
                for (int xx = 0; xx < 2; xx++) {
                    int pc = 0;
                    #pragma unroll
                    for (int r = 0; r < 3; r++) {
                        pc += __popcll(blk[yy + r][xx + 0] ^ wr[r * 3 + 0]);
                        pc += __popcll(blk[yy + r][xx + 1] ^ wr[r * 3 + 1]);
                        pc += __popcll(blk[yy + r][xx + 2] ^ wr[r * 3 + 2]);
                    }
                    int y = r0 + yy, xcv = c0 + xx;
                    int corr = 0;
                    if (y == 0)  corr += ET;
                    if (y == 13) corr += EB;
                    if (xcv == 0)  corr += EL;
                    if (xcv == 13) corr += ER;
                    if (y == 0 && xcv == 0)   corr -= e0;
                    if (y == 0 && xcv == 13)  corr -= e2;
                    if (y == 13 && xcv == 0)  corr -= e6;
                    if (y == 13 && xcv == 13) corr -= e8;
                    mx = max(mx, 576 - 2 * pc - corr);
                }
            }
            u32 mask = __ballot_sync(0xffffffffu, fmaf(A, (float)mx, Bc) >= 0.f);
            if (lane == 0) ((u32*)&sq[p])[half] = mask;
        }
    }
    __syncthreads();

    // ---- expand: bits -> bf16 +/-1 pairs ----
    u32* row = g_abf + (size_t)n * 1568;
    for (int i = t; i < 1568; i += 256) {
        int ke0 = 2 * i, ke1 = ke0 + 1;
        int c0 = ke0 / 49, p0 = ke0 - c0 * 49;
        int c1 = ke1 / 49, p1 = ke1 - c1 * 49;
        u32 v0 = ((sq[p0] >> c0) & 1ull) ? 0x3F80u : 0xBF80u;
        u32 v1 = ((sq[p1] >> c1) & 1ull) ? 0x3F80u : 0xBF80u;
        row[i] = v0 | (v1 << 16);
    }
}

// ---------------- fc1 via bf16 HMMA: C[64n x 128j] per CTA, warp tile 32x32 ----------------
// 8 warps (2 M x 4 N). dyn smem: A 2x8KB @0, B 2x16KB @16K = 48KB -> 3 CTAs/SM.
__global__ __launch_bounds__(256, 3) void fc1_hmma_kernel()
{
    extern __shared__ char smem[];
    u32 sb = smem_u32(smem);
    u32 stA[2] = { sb, sb + 8192u };
    u32 stB[2] = { sb + 16384u, sb + 32768u };

    int t = threadIdx.x;
    int w = t >> 5, lane = t & 31;
    int bx = blockIdx.x;
    int nblk = bx & 63, jblk = bx >> 6;      // 64 x 16 CTAs
    int n0 = nblk * 64, j0 = jblk * 128;
    int warp_m = w >> 2, warp_n = w & 3;     // 2 x 4
    int g = lane >> 2, tig = lane & 3;

    const char* aBase = (const char*)g_abf + (size_t)n0 * 6272;
    const char* bBase = (const char*)g_w1b + (size_t)j0 * 6272;

    {
        #pragma unroll
        for (int s = 0; s < 2; s++) {
            int idx = t + s * 256;
            int row = idx >> 3, ch = idx & 7;
            CP_ASYNC16(stA[0] + SWZ128(row * 128 + ch * 16), aBase + (size_t)row * 6272 + ch * 16);
        }
        #pragma unroll
        for (int s = 0; s < 4; s++) {
            int idx = t + s * 256;
            int row = idx >> 3, ch = idx & 7;
            CP_ASYNC16(stB[0] + SWZ128(row * 128 + ch * 16), bBase + (size_t)row * 6272 + ch * 16);
        }
        CP_COMMIT();
    }

    float acc[2][4][4];
    #pragma unroll
    for (int mi = 0; mi < 2; mi++)
        #pragma unroll
        for (int ni = 0; ni < 4; ni++)
            #pragma unroll
            for (int cc = 0; cc < 4; cc++) acc[mi][ni][cc] = 0.f;

    int aRowL = warp_m * 32 + (lane & 15);
    int aHi = lane >> 4;
    int bRowL = warp_n * 32 + (lane & 7) + ((lane >> 4) & 1) * 8;
    int bHi = (lane >> 3) & 1;

    for (int c = 0; c < 49; c++) {
        int buf = c & 1;
        if (c + 1 < 49) {
            int nb = buf ^ 1;
            size_t koff = (size_t)(c + 1) * 128;
            #pragma unroll
            for (int s = 0; s < 2; s++) {
                int idx = t + s * 256;
                int row = idx >> 3, ch = idx & 7;
                CP_ASYNC16(stA[nb] + SWZ128(row * 128 + ch * 16), aBase + (size_t)row * 6272 + koff + ch * 16);
            }
            #pragma unroll
            for (int s = 0; s < 4; s++) {
                int idx = t + s * 256;
                int row = idx >> 3, ch = idx & 7;
                CP_ASYNC16(stB[nb] + SWZ128(row * 128 + ch * 16), bBase + (size_t)row * 6272 + koff + ch * 16);
            }
            CP_COMMIT();
            asm volatile("cp.async.wait_group 1;" ::: "memory");
        } else {
            asm volatile("cp.async.wait_group 0;" ::: "memory");
        }
        __syncthreads();

        #pragma unroll
        for (int ks = 0; ks < 4; ks++) {
            u32 af[2][4];
            #pragma unroll
            for (int mi = 0; mi < 2; mi++) {
                int row = aRowL + mi * 16;
                int ch = (ks * 2 + aHi) ^ (row & 7);
                ldsm4(af[mi][0], af[mi][1], af[mi][2], af[mi][3], stA[buf] + row * 128 + ch * 16);
            }
            u32 bf[2][4];
            #pragma unroll
            for (int np = 0; np < 2; np++) {
                int row = bRowL + np * 16;
                int ch = (ks * 2 + bHi) ^ (row & 7);
                ldsm4(bf[np][0], bf[np][1], bf[np][2], bf[np][3], stB[buf] + row * 128 + ch * 16);
            }
            #pragma unroll
            for (int mi = 0; mi < 2; mi++) {
                hmma_bf16(acc[mi][0], af[mi][0], af[mi][1], af[mi][2], af[mi][3], bf[0][0], bf[0][1]);
                hmma_bf16(acc[mi][1], af[mi][0], af[mi][1], af[mi][2], af[mi][3], bf[0][2], bf[0][3]);
                hmma_bf16(acc[mi][2], af[mi][0], af[mi][1], af[mi][2], af[mi][3], bf[1][0], bf[1][1]);
                hmma_bf16(acc[mi][3], af[mi][0], af[mi][1], af[mi][2], af[mi][3], bf[1][2], bf[1][3]);
            }
        }
        __syncthreads();
    }

    float A3v[4][2], B3v[4][2];
    #pragma unroll
    for (int ni = 0; ni < 4; ni++)
        #pragma unroll
        for (int cc = 0; cc < 2; cc++) {
            int j = j0 + warp_n * 32 + ni * 8 + tig * 2 + cc;
            A3v[ni][cc] = g_A3[j];
            B3v[ni][cc] = g_B3[j];
        }
    int wi = jblk * 4 + warp_n;
    #pragma unroll
    for (int mi = 0; mi < 2; mi++) {
        u32 v0 = 0, v1 = 0;
        #pragma unroll
        for (int ni = 0; ni < 4; ni++)
            #pragma unroll
            for (int cc = 0; cc < 2; cc++) {
                int pos = ni * 8 + tig * 2 + cc;
                v0 |= (u32)(fmaf(A3v[ni][cc], acc[mi][ni][cc],     B3v[ni][cc]) >= 0.f) << pos;
                v1 |= (u32)(fmaf(A3v[ni][cc], acc[mi][ni][2 + cc], B3v[ni][cc]) >= 0.f) << pos;
            }
        v0 |= __shfl_xor_sync(0xffffffffu, v0, 1);
        v0 |= __shfl_xor_sync(0xffffffffu, v0, 2);
        v1 |= __shfl_xor_sync(0xffffffffu, v1, 1);
        v1 |= __shfl_xor_sync(0xffffffffu, v1, 2);
        if (tig == 0) {
            int row0 = n0 + warp_m * 32 + mi * 16 + g;
            g_q3[(size_t)row0 * 64 + wi] = v0;
            g_q3[(size_t)(row0 + 8) * 64 + wi] = v1;
        }
    }
}

// ---------------- fc2 + scale ----------------
__global__ __launch_bounds__(256) void fc2_kernel(const float* __restrict__ fc2_b,
                                                  const float* __restrict__ scale,
                                                  float* __restrict__ out)
{
    __shared__ u32 q3[16 * 64];
    __shared__ u32 f2[640];
    int n0 = blockIdx.x * 16;
    int t = threadIdx.x;
    for (int i = t; i < 1024; i += 256) q3[i] = g_q3[n0 * 64 + i];
    for (int i = t; i < 640; i += 256) f2[i] = g_f2p[i];
    __syncthreads();
    if (t < 160) {
        int nl = t / 10, k = t % 10;
        int pc = 0;
        #pragma unroll 8
        for (int wi = 0; wi < 64; wi++) pc += __popc(q3[nl * 64 + wi] ^ f2[k * 64 + wi]);
        out[(n0 + nl) * 10 + k] = ((float)(2048 - 2 * pc) + fc2_b[k]) * scale[0];
    }
}

// ---------------- launch ----------------
extern "C" void kernel_launch(void* const* d_in, const int* in_sizes, int n_in,
                              void* d_out, int out_size)
{
    const float* x   = (const float*)d_in[0];
    const float* c1w = (const float*)d_in[1];
    const float* c1b = (const float*)d_in[2];
    const float* c2w = (const float*)d_in[3];
    const float* c2b = (const float*)d_in[4];
    const float* f1w = (const float*)d_in[5];
    const float* f1b = (const float*)d_in[6];
    const float* f2w = (const float*)d_in[7];
    const float* f2b = (const float*)d_in[8];
    const float* g1  = (const float*)d_in[9];
    const float* be1 = (const float*)d_in[10];
    const float* mu1 = (const float*)d_in[11];
    const float* va1 = (const float*)d_in[12];
    const float* g2  = (const float*)d_in[13];
    const float* be2 = (const float*)d_in[14];
    const float* mu2 = (const float*)d_in[15];
    const float* va2 = (const float*)d_in[16];
    const float* g3  = (const float*)d_in[17];
    const float* be3 = (const float*)d_in[18];
    const float* mu3 = (const float*)d_in[19];
    const float* va3 = (const float*)d_in[20];
    const float* scl = (const float*)d_in[21];

    int B = in_sizes[0] / 784;   // 4096

    cudaFuncSetAttribute(fc1_hmma_kernel, cudaFuncAttributeMaxDynamicSharedMemorySize, 49152);

    int prep_items = 2048 * 784 + 640 + 576 + 64 + 64 + 2048;
    prep_kernel<<<(prep_items + 255) / 256, 256>>>(f1w, f2w, c2w, c1w, c1b,
                                                   g1, be1, mu1, va1,
                                                   c2b, g2, be2, mu2, va2,
                                                   f1b, g3, be3, mu3, va3);
    conv_kernel<<<B, 256>>>(x);
    fc1_hmma_kernel<<<(B / 64) * 16, 256, 49152>>>();
    fc2_kernel<<<B / 16, 256>>>(f2b, scl, (float*)d_out);
}